// round 1
// baseline (speedup 1.0000x reference)
#include <cuda_runtime.h>

#define NB 512
#define NS 1024
#define NL 64
#define NC 66

// ---- packed f32x2 helpers (Blackwell FFMA2 path, PTX f32x2 ops) ----
__device__ __forceinline__ unsigned long long fma2_(unsigned long long a, unsigned long long b, unsigned long long c) {
    unsigned long long d;
    asm("fma.rn.f32x2 %0, %1, %2, %3;" : "=l"(d) : "l"(a), "l"(b), "l"(c));
    return d;
}
__device__ __forceinline__ unsigned long long add2_(unsigned long long a, unsigned long long b) {
    unsigned long long d;
    asm("add.rn.f32x2 %0, %1, %2;" : "=l"(d) : "l"(a), "l"(b));
    return d;
}
__device__ __forceinline__ unsigned long long pack2_(float lo, float hi) {
    unsigned long long d;
    asm("mov.b64 %0, {%1, %2};" : "=l"(d) : "f"(lo), "f"(hi));
    return d;
}
__device__ __forceinline__ float2 unpack2_(unsigned long long v) {
    float lo, hi;
    asm("mov.b64 {%0, %1}, %2;" : "=f"(lo), "=f"(hi) : "l"(v));
    return make_float2(lo, hi);
}
// named barrier over one 64-thread group (2 warps)
__device__ __forceinline__ void barg(int id) {
    asm volatile("bar.sync %0, 64;" :: "r"(id) : "memory");
}

__global__ void zero_out_kernel(float* out) { out[0] = 0.0f; }

__global__ void __launch_bounds__(256, 1)
crf_fwd_kernel(const float* __restrict__ pred,
               const int*   __restrict__ ref,
               const int*   __restrict__ seq_len,
               const float* __restrict__ trans,
               float*       __restrict__ out)
{
    // per-group p double buffer (4 groups x 2 bufs x 64 floats), 16B aligned
    __shared__ __align__(16) float pbuf[4][2][64];
    __shared__ float red[4][4];

    const int g = threadIdx.x >> 6;      // group (batch slot) within CTA: 0..3
    const int j = threadIdx.x & 63;      // state index 0..63
    const int b = (blockIdx.x << 2) + g; // batch index 0..511
    const int Lb = seq_len[b];           // 1..1024

    // ---- one-time: packed E column e2[k] = (exp(T[2k][j]), exp(T[2k+1][j])) ----
    unsigned long long e2[32];
#pragma unroll
    for (int k = 0; k < 32; ++k) {
        float elo = __expf(trans[(2 * k)     * NC + j]);
        float ehi = __expf(trans[(2 * k + 1) * NC + j]);
        e2[k] = pack2_(elo, ehi);
    }
    const float Te = __expf(trans[j * NC + 65]);  // end-transition (linear)
    const float Ts = trans[64 * NC + j];          // start-transition (log)

    const float* pb = pred + (size_t)b * NS * NL;

    // ---- init: q1 = exp(pred[0] + Ts), offset o1 = 0 ----
    float q = __expf(pb[j] + Ts);
    int wr = 0;
    pbuf[g][wr][j] = q;

    // prefetch pipeline for pred rows (depth 2 regs + L2 prefetch)
    float pr_a = pb[(size_t)(Lb > 1 ? 1 : 0) * NL + j];  // row for step t=2
    float pr_b = pb[(size_t)(Lb > 2 ? 2 : 0) * NL + j];  // row for step t=3
    float w = __expf(pr_a - 4.0f);                        // weight for t=2
    int esum = 0;

    barg(g);

    for (int t = 2; t <= Lb; ++t) {
        const float* rp = pbuf[g][wr];   // q_{t-1}
        wr ^= 1;
        const ulonglong2* rp2 = (const ulonglong2*)rp;

        // dot: d = sum_i q_{t-1}[i] * E[i][j]   (16x LDS.128 broadcast + 32x FFMA2)
        unsigned long long a0 = 0, a1 = 0, a2 = 0, a3 = 0;
#pragma unroll
        for (int k = 0; k < 8; ++k) {
            ulonglong2 v0 = rp2[2 * k];
            ulonglong2 v1 = rp2[2 * k + 1];
            a0 = fma2_(v0.x, e2[4 * k + 0], a0);
            a1 = fma2_(v0.y, e2[4 * k + 1], a1);
            a2 = fma2_(v1.x, e2[4 * k + 2], a2);
            a3 = fma2_(v1.y, e2[4 * k + 3], a3);
        }
        unsigned long long s01 = add2_(a0, a1);
        unsigned long long s23 = add2_(a2, a3);
        unsigned long long ss  = add2_(s01, s23);
        float2 sf = unpack2_(ss);
        float d = sf.x + sf.y;

        float qn = d * w;

        // deterministic renormalization every 8 steps (exact power of 2)
        if ((t & 7) == 0) {
            float m = 0.0f;
            const float4* rf = (const float4*)rp;
#pragma unroll
            for (int k = 0; k < 16; ++k) {
                float4 v = rf[k];
                m = fmaxf(m, fmaxf(fmaxf(v.x, v.y), fmaxf(v.z, v.w)));
            }
            int e = ((__float_as_int(m) >> 23) & 0xFF) - 127;
            e = max(-60, min(60, e));
            float f = __int_as_float((unsigned)(127 - e) << 23);  // 2^{-e}
            qn *= f;
            esum += e;
        }

        pbuf[g][wr][j] = qn;
        q = qn;

        // prepare next step's weight off the critical chain
        w = __expf(pr_b - 4.0f);                    // for step t+1 (pred row t)
        int nrow = t + 1; if (nrow > Lb - 1) nrow = Lb - 1;
        pr_b = pb[(size_t)nrow * NL + j];           // pred row for step t+2
        int prow = t + 4; if (prow > Lb - 1) prow = Lb - 1;
        asm volatile("prefetch.global.L2 [%0];" :: "l"(pb + (size_t)prow * NL + j));

        barg(g);
    }

    // ---- forward terminal: v = q_L[j] * exp(T[j][65]) ----
    float v = q * Te;

    // ---- real path score (gather), thread-strided over time ----
    float rsum = 0.0f;
    const int* rb = ref + (size_t)b * NS;
    for (int t = j; t < Lb; t += 64) {
        int r = rb[t];
        int prev = (t == 0) ? 64 : rb[t - 1];
        rsum += pb[(size_t)t * NL + r] + trans[prev * NC + r];
    }
    if (j == 0) rsum += trans[rb[Lb - 1] * NC + 65];

    // ---- reduce v and rsum over the 64-thread group ----
#pragma unroll
    for (int o = 16; o; o >>= 1) {
        v    += __shfl_xor_sync(0xFFFFFFFFu, v, o);
        rsum += __shfl_xor_sync(0xFFFFFFFFu, rsum, o);
    }
    if ((j & 31) == 0) {
        red[g][(j >> 5) * 2 + 0] = v;
        red[g][(j >> 5) * 2 + 1] = rsum;
    }
    barg(g);
    if (j == 0) {
        float s  = red[g][0] + red[g][2];
        float rs = red[g][1] + red[g][3];
        float o_off = 4.0f * (float)(Lb - 1) + 0.6931471805599453f * (float)esum;
        atomicAdd(out, o_off + __logf(s) - rs);
    }
}

extern "C" void kernel_launch(void* const* d_in, const int* in_sizes, int n_in,
                              void* d_out, int out_size)
{
    const float* pred  = (const float*)d_in[0];
    const int*   ref   = (const int*)d_in[1];
    const int*   seq   = (const int*)d_in[2];
    const float* trans = (const float*)d_in[3];
    float* out = (float*)d_out;

    zero_out_kernel<<<1, 1>>>(out);
    crf_fwd_kernel<<<NB / 4, 256>>>(pred, ref, seq, trans, out);
}